// round 4
// baseline (speedup 1.0000x reference)
#include <cuda_runtime.h>
#include <cstdint>

#define Bsz  4
#define Nseq 2048
#define Cdim 768
#define Hn   12
#define Dh   64
#define Mrows (Bsz * Nseq)   // 8192
#define SCALE_F 0.125f

// Scratch (device globals)
__device__ float g_q[Mrows * Cdim];    // [B,H,N,D] (tf32-rounded)
__device__ float g_k[Mrows * Cdim];
__device__ float g_v[Mrows * Cdim];
__device__ float g_o[Mrows * Cdim];    // [B,N,C]   (tf32-rounded)
__device__ float g_uc[Mrows];
__device__ float g_xq[Mrows * Cdim];   // tf32-rounded inputs
__device__ float g_xk[Mrows * Cdim];
__device__ float g_xv[Mrows * Cdim];
__device__ float g_wq[Cdim * Cdim];    // tf32-rounded weights
__device__ float g_wk[Cdim * Cdim];
__device__ float g_wv[Cdim * Cdim];
__device__ float g_wp[Cdim * Cdim];

// ---------------------------------------------------------------------------
__device__ __forceinline__ uint32_t f2tf(float x) {
    uint32_t u;
    asm("cvt.rna.tf32.f32 %0, %1;" : "=r"(u) : "f"(x));
    return u;
}
__device__ __forceinline__ uint32_t smem_u32(const void* p) {
    uint32_t a;
    asm("{ .reg .u64 t; cvta.to.shared.u64 t, %1; cvt.u32.u64 %0, t; }" : "=r"(a) : "l"(p));
    return a;
}
#define CP16(dst, src) \
    asm volatile("cp.async.cg.shared.global [%0], [%1], 16;" :: "r"(dst), "l"(src))
#define CP_COMMIT() asm volatile("cp.async.commit_group;" ::: "memory")
#define CP_WAIT(n)  asm volatile("cp.async.wait_group %0;" :: "n"(n) : "memory")

__device__ __forceinline__ void mma8(float* d,
    uint32_t a0, uint32_t a1, uint32_t a2, uint32_t a3,
    uint32_t b0, uint32_t b1)
{
    asm("mma.sync.aligned.m16n8k8.row.col.f32.tf32.tf32.f32 "
        "{%0,%1,%2,%3},{%4,%5,%6,%7},{%8,%9},{%0,%1,%2,%3};"
        : "+f"(d[0]), "+f"(d[1]), "+f"(d[2]), "+f"(d[3])
        : "r"(a0), "r"(a1), "r"(a2), "r"(a3), "r"(b0), "r"(b1));
}

// ---------------------------------------------------------------------------
// Elementwise tf32 rounding (rna) into scratch
// ---------------------------------------------------------------------------
__global__ void roundtf(const float* __restrict__ x, float* __restrict__ y, int n)
{
    int i = (blockIdx.x * blockDim.x + threadIdx.x) * 4;
    if (i >= n) return;
    float4 v = *(const float4*)(x + i);
    uint4 u = make_uint4(f2tf(v.x), f2tf(v.y), f2tf(v.z), f2tf(v.w));
    *(uint4*)(y + i) = u;
}

// ---------------------------------------------------------------------------
// TF32 GEMM, cp.async 2-stage pipeline: Y[M,Nc] = A @ W^T.
// A, W pre-rounded to tf32. 128x128 tile, BK=32, 8 warps (64x32 each).
// smem stage: As[128][36] + Ws[128][36] floats; 2 stages = 73728 B.
// ---------------------------------------------------------------------------
#define GP_STG  (2 * 128 * 36)          // floats per stage (A+W)
#define GP_SMEM (2 * GP_STG * 4)        // 73728 bytes

template<int HEAD_REMAP, int HAS_BIAS>
__global__ __launch_bounds__(256, 2) void gemm_cp(
    const float* __restrict__ A, const float* __restrict__ W,
    const float* __restrict__ bias, float* __restrict__ Y)
{
    extern __shared__ float smem[];
    int t = threadIdx.x, wid = t >> 5, lane = t & 31;
    int wm = (wid >> 2) * 64;
    int wn = (wid & 3) * 32;
    int r = lane >> 2, c = lane & 3;
    int m0 = blockIdx.y * 128, n0 = blockIdx.x * 128;

    float acc[4][4][4];
#pragma unroll
    for (int mt = 0; mt < 4; mt++)
#pragma unroll
        for (int nt = 0; nt < 4; nt++)
#pragma unroll
            for (int i = 0; i < 4; i++) acc[mt][nt][i] = 0.0f;

    // cp.async mapping: 1024 16B-chunks per tensor; 4 chunks A + 4 chunks W / thread
    uint32_t sbase = smem_u32(smem);

#define GP_PREFETCH(kt) do {                                                       \
    int _s = (kt) & 1;                                                             \
    uint32_t _dA = sbase + (_s * GP_STG) * 4;                                      \
    uint32_t _dW = _dA + 128 * 36 * 4;                                             \
    int _kb = (kt) * 32;                                                           \
    _Pragma("unroll")                                                              \
    for (int j = 0; j < 4; j++) {                                                  \
        int idx = t * 4 + j;                                                       \
        int row = idx >> 3, ch = idx & 7;                                          \
        CP16(_dA + (row * 36 + ch * 4) * 4,                                        \
             A + (size_t)(m0 + row) * Cdim + _kb + ch * 4);                        \
        CP16(_dW + (row * 36 + ch * 4) * 4,                                        \
             W + (size_t)(n0 + row) * Cdim + _kb + ch * 4);                        \
    }                                                                              \
} while (0)

    GP_PREFETCH(0);
    CP_COMMIT();

    const int NT = Cdim / 32;   // 24
    for (int kt = 0; kt < NT; kt++) {
        if (kt + 1 < NT) {
            GP_PREFETCH(kt + 1);
            CP_COMMIT();
            CP_WAIT(1);
        } else {
            CP_WAIT(0);
        }
        __syncthreads();

        const uint32_t* As = (const uint32_t*)(smem + (kt & 1) * GP_STG);
        const uint32_t* Bs = As + 128 * 36;
#pragma unroll
        for (int kk = 0; kk < 32; kk += 8) {
            uint32_t a[4][4], b[4][2];
#pragma unroll
            for (int mt = 0; mt < 4; mt++) {
                a[mt][0] = As[(wm + mt * 16 + r    ) * 36 + kk + c    ];
                a[mt][1] = As[(wm + mt * 16 + r + 8) * 36 + kk + c    ];
                a[mt][2] = As[(wm + mt * 16 + r    ) * 36 + kk + c + 4];
                a[mt][3] = As[(wm + mt * 16 + r + 8) * 36 + kk + c + 4];
            }
#pragma unroll
            for (int nt = 0; nt < 4; nt++) {
                b[nt][0] = Bs[(wn + nt * 8 + r) * 36 + kk + c    ];
                b[nt][1] = Bs[(wn + nt * 8 + r) * 36 + kk + c + 4];
            }
#pragma unroll
            for (int mt = 0; mt < 4; mt++)
#pragma unroll
                for (int nt = 0; nt < 4; nt++)
                    mma8(acc[mt][nt], a[mt][0], a[mt][1], a[mt][2], a[mt][3],
                         b[nt][0], b[nt][1]);
        }
        __syncthreads();
    }

    // Epilogue
#pragma unroll
    for (int mt = 0; mt < 4; mt++) {
#pragma unroll
        for (int nt = 0; nt < 4; nt++) {
            int n = n0 + wn + nt * 8 + 2 * c;
            int mA = m0 + wm + mt * 16 + r;
            int mB = mA + 8;
            if (HEAD_REMAP) {
                // round to tf32 so downstream mma truncation is exact
                uint2 lo = make_uint2(f2tf(acc[mt][nt][0]), f2tf(acc[mt][nt][1]));
                uint2 hi = make_uint2(f2tf(acc[mt][nt][2]), f2tf(acc[mt][nt][3]));
                int h = n >> 6, d = n & 63;
                int bA = mA >> 11, nA = mA & (Nseq - 1);
                int bB = mB >> 11, nB = mB & (Nseq - 1);
                *(uint2*)&Y[(((size_t)(bA * Hn + h) * Nseq + nA) << 6) + d] = lo;
                *(uint2*)&Y[(((size_t)(bB * Hn + h) * Nseq + nB) << 6) + d] = hi;
            } else {
                float2 lo = make_float2(acc[mt][nt][0], acc[mt][nt][1]);
                float2 hi = make_float2(acc[mt][nt][2], acc[mt][nt][3]);
                if (HAS_BIAS) {
                    float2 bb = *(const float2*)&bias[n];
                    lo.x += bb.x; lo.y += bb.y; hi.x += bb.x; hi.y += bb.y;
                }
                *(float2*)&Y[(size_t)mA * Cdim + n] = lo;
                *(float2*)&Y[(size_t)mB * Cdim + n] = hi;
            }
        }
    }
}

// ---------------------------------------------------------------------------
__global__ void uc_kernel(const float* __restrict__ xu, float* __restrict__ uc)
{
    int warp = (blockIdx.x * blockDim.x + threadIdx.x) >> 5;
    int lane = threadIdx.x & 31;
    if (warp >= Mrows) return;
    const float* row = xu + (size_t)warp * Cdim;
    float s = 0.0f;
#pragma unroll
    for (int i = 0; i < Cdim / 32; i++) s += row[lane + i * 32];
#pragma unroll
    for (int m = 16; m; m >>= 1) s += __shfl_xor_sync(0xffffffffu, s, m);
    if (lane == 0) uc[warp] = s * (1.0f / Cdim);
}

// ---------------------------------------------------------------------------
// Fused attention (legacy tf32 mma), cp.async K/V staging. K/V pre-rounded.
// ---------------------------------------------------------------------------
__global__ __launch_bounds__(256, 2) void attn_tf32(
    const float* __restrict__ Q, const float* __restrict__ K,
    const float* __restrict__ V, const float* __restrict__ UC,
    float* __restrict__ O)
{
    extern __shared__ uint32_t sm[];
    uint32_t* Qs = sm;                    // [128][68]
    uint32_t* Ks = Qs + 128 * 68;         // [64][68]
    uint32_t* Vs = Ks + 64 * 68;          // [64][68]
    uint32_t* Ps = Vs + 64 * 68;          // [128][68]

    int t = threadIdx.x, wid = t >> 5, lane = t & 31;
    int r = lane >> 2, c = lane & 3;
    int bh = blockIdx.y;
    int b = bh / Hn, h = bh - b * Hn;
    int q0 = blockIdx.x * 128;

    const float* Qb = Q + ((size_t)bh * Nseq + q0) * Dh;
    const float* Kb = K + (size_t)bh * Nseq * Dh;
    const float* Vb = V + (size_t)bh * Nseq * Dh;

    uint32_t ks_addr = smem_u32(Ks);
    uint32_t vs_addr = smem_u32(Vs);

    // Stage Q with SCALE*uc folded in (re-round after scaling)
    {
        int row = t >> 1, d0 = (t & 1) * 32;
        float sc = UC[b * Nseq + q0 + row] * SCALE_F;
#pragma unroll
        for (int i = 0; i < 32; i += 4) {
            float4 v = *(const float4*)(Qb + (size_t)row * Dh + d0 + i);
            Qs[row * 68 + d0 + i + 0] = f2tf(v.x * sc);
            Qs[row * 68 + d0 + i + 1] = f2tf(v.y * sc);
            Qs[row * 68 + d0 + i + 2] = f2tf(v.z * sc);
            Qs[row * 68 + d0 + i + 3] = f2tf(v.w * sc);
        }
    }

    float m_[2] = { -1e30f, -1e30f };
    float l_[2] = { 0.0f, 0.0f };
    float o[8][4];
#pragma unroll
    for (int nt = 0; nt < 8; nt++)
#pragma unroll
        for (int i = 0; i < 4; i++) o[nt][i] = 0.0f;

    int qrow0 = wid * 16 + r;
    int qrow1 = qrow0 + 8;

    for (int kt = 0; kt < Nseq; kt += 64) {
        __syncthreads();   // previous K/V/P fully consumed (also orders Q stage, iter 0)

        // cp.async K and V tiles (64 rows x 64 floats each)
#pragma unroll
        for (int j = 0; j < 4; j++) {
            int idx = t * 4 + j;
            int row = idx >> 4, ch = idx & 15;
            CP16(ks_addr + (row * 68 + ch * 4) * 4,
                 Kb + (size_t)(kt + row) * Dh + ch * 4);
            CP16(vs_addr + (row * 68 + ch * 4) * 4,
                 Vb + (size_t)(kt + row) * Dh + ch * 4);
        }
        CP_COMMIT();
        CP_WAIT(0);
        __syncthreads();

        // S = Q * K^T  (warp: 16 x 64)
        float s[8][4];
#pragma unroll
        for (int nt = 0; nt < 8; nt++)
#pragma unroll
            for (int i = 0; i < 4; i++) s[nt][i] = 0.0f;

#pragma unroll
        for (int ks = 0; ks < 64; ks += 8) {
            uint32_t a0 = Qs[qrow0 * 68 + ks + c];
            uint32_t a1 = Qs[qrow1 * 68 + ks + c];
            uint32_t a2 = Qs[qrow0 * 68 + ks + c + 4];
            uint32_t a3 = Qs[qrow1 * 68 + ks + c + 4];
#pragma unroll
            for (int nt = 0; nt < 8; nt++) {
                uint32_t b0 = Ks[(nt * 8 + r) * 68 + ks + c];
                uint32_t b1 = Ks[(nt * 8 + r) * 68 + ks + c + 4];
                mma8(s[nt], a0, a1, a2, a3, b0, b1);
            }
        }

        // Online softmax (2 rows per thread; stats across 4 lanes)
        float mx0 = -1e30f, mx1 = -1e30f;
#pragma unroll
        for (int nt = 0; nt < 8; nt++) {
            mx0 = fmaxf(mx0, fmaxf(s[nt][0], s[nt][1]));
            mx1 = fmaxf(mx1, fmaxf(s[nt][2], s[nt][3]));
        }
        mx0 = fmaxf(mx0, __shfl_xor_sync(0xffffffffu, mx0, 1));
        mx0 = fmaxf(mx0, __shfl_xor_sync(0xffffffffu, mx0, 2));
        mx1 = fmaxf(mx1, __shfl_xor_sync(0xffffffffu, mx1, 1));
        mx1 = fmaxf(mx1, __shfl_xor_sync(0xffffffffu, mx1, 2));

        float mn0 = fmaxf(m_[0], mx0);
        float mn1 = fmaxf(m_[1], mx1);
        float cor0 = __expf(m_[0] - mn0);
        float cor1 = __expf(m_[1] - mn1);
        m_[0] = mn0; m_[1] = mn1;

        float sum0 = 0.0f, sum1 = 0.0f;
#pragma unroll
        for (int nt = 0; nt < 8; nt++) {
            float p0 = __expf(s[nt][0] - mn0);
            float p1 = __expf(s[nt][1] - mn0);
            float p2 = __expf(s[nt][2] - mn1);
            float p3 = __expf(s[nt][3] - mn1);
            sum0 += p0 + p1;
            sum1 += p2 + p3;
            *(uint2*)&Ps[qrow0 * 68 + nt * 8 + 2 * c] = make_uint2(f2tf(p0), f2tf(p1));
            *(uint2*)&Ps[qrow1 * 68 + nt * 8 + 2 * c] = make_uint2(f2tf(p2), f2tf(p3));
        }
        sum0 += __shfl_xor_sync(0xffffffffu, sum0, 1);
        sum0 += __shfl_xor_sync(0xffffffffu, sum0, 2);
        sum1 += __shfl_xor_sync(0xffffffffu, sum1, 1);
        sum1 += __shfl_xor_sync(0xffffffffu, sum1, 2);
        l_[0] = l_[0] * cor0 + sum0;
        l_[1] = l_[1] * cor1 + sum1;

#pragma unroll
        for (int nt = 0; nt < 8; nt++) {
            o[nt][0] *= cor0; o[nt][1] *= cor0;
            o[nt][2] *= cor1; o[nt][3] *= cor1;
        }

        __syncwarp();   // P rows per-warp private

        // O += P * V
#pragma unroll
        for (int ks2 = 0; ks2 < 64; ks2 += 8) {
            uint32_t a0 = Ps[qrow0 * 68 + ks2 + c];
            uint32_t a1 = Ps[qrow1 * 68 + ks2 + c];
            uint32_t a2 = Ps[qrow0 * 68 + ks2 + c + 4];
            uint32_t a3 = Ps[qrow1 * 68 + ks2 + c + 4];
#pragma unroll
            for (int nt = 0; nt < 8; nt++) {
                uint32_t b0 = Vs[(ks2 + c    ) * 68 + nt * 8 + r];
                uint32_t b1 = Vs[(ks2 + c + 4) * 68 + nt * 8 + r];
                mma8(o[nt], a0, a1, a2, a3, b0, b1);
            }
        }
        __syncwarp();
    }

    // Epilogue: normalize, round to tf32 (exact for final GEMM), write [B,N,C]
    float inv0 = 1.0f / l_[0];
    float inv1 = 1.0f / l_[1];
    int qg0 = q0 + qrow0;
    int qg1 = q0 + qrow1;
#pragma unroll
    for (int nt = 0; nt < 8; nt++) {
        int d = h * Dh + nt * 8 + 2 * c;
        *(uint2*)&O[(size_t)(b * Nseq + qg0) * Cdim + d] =
            make_uint2(f2tf(o[nt][0] * inv0), f2tf(o[nt][1] * inv0));
        *(uint2*)&O[(size_t)(b * Nseq + qg1) * Cdim + d] =
            make_uint2(f2tf(o[nt][2] * inv1), f2tf(o[nt][3] * inv1));
    }
}

// ---------------------------------------------------------------------------
extern "C" void kernel_launch(void* const* d_in, const int* in_sizes, int n_in,
                              void* d_out, int out_size)
{
    const float* x_q = (const float*)d_in[0];
    const float* x_k = (const float*)d_in[1];
    const float* x_v = (const float*)d_in[2];
    const float* x_u = (const float*)d_in[3];
    const float* Wq  = (const float*)d_in[4];
    const float* Wk  = (const float*)d_in[5];
    const float* Wv  = (const float*)d_in[6];
    const float* Wp  = (const float*)d_in[7];
    const float* bp  = (const float*)d_in[8];
    float* out = (float*)d_out;

    float *gq, *gk, *gv, *go, *guc;
    float *gxq, *gxk, *gxv, *gwq, *gwk, *gwv, *gwp;
    cudaGetSymbolAddress((void**)&gq,  g_q);
    cudaGetSymbolAddress((void**)&gk,  g_k);
    cudaGetSymbolAddress((void**)&gv,  g_v);
    cudaGetSymbolAddress((void**)&go,  g_o);
    cudaGetSymbolAddress((void**)&guc, g_uc);
    cudaGetSymbolAddress((void**)&gxq, g_xq);
    cudaGetSymbolAddress((void**)&gxk, g_xk);
    cudaGetSymbolAddress((void**)&gxv, g_xv);
    cudaGetSymbolAddress((void**)&gwq, g_wq);
    cudaGetSymbolAddress((void**)&gwk, g_wk);
    cudaGetSymbolAddress((void**)&gwv, g_wv);
    cudaGetSymbolAddress((void**)&gwp, g_wp);

    const int ATTN_SMEM = (128 * 68 + 64 * 68 + 64 * 68 + 128 * 68) * 4;  // 104448
    cudaFuncSetAttribute(attn_tf32, cudaFuncAttributeMaxDynamicSharedMemorySize, ATTN_SMEM);
    cudaFuncSetAttribute(gemm_cp<1, 0>, cudaFuncAttributeMaxDynamicSharedMemorySize, GP_SMEM);
    cudaFuncSetAttribute(gemm_cp<0, 1>, cudaFuncAttributeMaxDynamicSharedMemorySize, GP_SMEM);

    // Pre-round inputs + weights to tf32 (rna)
    const int NX = Mrows * Cdim;       // 6291456
    const int NW = Cdim * Cdim;        // 589824
    roundtf<<<NX / 1024, 256>>>(x_q, gxq, NX);
    roundtf<<<NX / 1024, 256>>>(x_k, gxk, NX);
    roundtf<<<NX / 1024, 256>>>(x_v, gxv, NX);
    roundtf<<<NW / 1024, 256>>>(Wq, gwq, NW);
    roundtf<<<NW / 1024, 256>>>(Wk, gwk, NW);
    roundtf<<<NW / 1024, 256>>>(Wv, gwv, NW);
    roundtf<<<NW / 1024, 256>>>(Wp, gwp, NW);

    uc_kernel<<<Mrows / 8, 256>>>(x_u, guc);

    dim3 gemm_grid(Cdim / 128, Mrows / 128);   // (6, 64)
    gemm_cp<1, 0><<<gemm_grid, 256, GP_SMEM>>>(gxq, gwq, nullptr, gq);
    gemm_cp<1, 0><<<gemm_grid, 256, GP_SMEM>>>(gxk, gwk, nullptr, gk);
    gemm_cp<1, 0><<<gemm_grid, 256, GP_SMEM>>>(gxv, gwv, nullptr, gv);

    dim3 attn_grid(Nseq / 128, Bsz * Hn);      // (16, 48)
    attn_tf32<<<attn_grid, 256, ATTN_SMEM>>>(gq, gk, gv, guc, go);

    gemm_cp<0, 1><<<gemm_grid, 256, GP_SMEM>>>(go, gwp, bp, out);
}

// round 5
// speedup vs baseline: 2.1426x; 2.1426x over previous
#include <cuda_runtime.h>
#include <cuda_fp16.h>
#include <cstdint>

#define Bsz  4
#define Nseq 2048
#define Cdim 768
#define Hn   12
#define Dh   64
#define Mrows (Bsz * Nseq)   // 8192
#define SCALE_F 0.125f

// Scratch (device globals; halves stored as __half)
__device__ __half g_xq[Mrows * Cdim];
__device__ __half g_xk[Mrows * Cdim];
__device__ __half g_xv[Mrows * Cdim];
__device__ __half g_wq[Cdim * Cdim];
__device__ __half g_wk[Cdim * Cdim];
__device__ __half g_wv[Cdim * Cdim];
__device__ __half g_wp[Cdim * Cdim];
__device__ __half g_q[Mrows * Cdim];   // [B,H,N,D], uc*SCALE folded
__device__ __half g_k[Mrows * Cdim];   // [B,H,N,D]
__device__ __half g_v[Mrows * Cdim];   // [B,H,N,D]
__device__ __half g_o[Mrows * Cdim];   // [B,N,C]
__device__ float  g_uc[Mrows];

// ---------------------------------------------------------------------------
__device__ __forceinline__ uint32_t smem_u32(const void* p) {
    uint32_t a;
    asm("{ .reg .u64 t; cvta.to.shared.u64 t, %1; cvt.u32.u64 %0, t; }" : "=r"(a) : "l"(p));
    return a;
}
__device__ __forceinline__ uint32_t packh2(float a, float b) {
    __half2 h = __floats2half2_rn(a, b);
    return *(uint32_t*)&h;
}
#define CP16(dst, src) \
    asm volatile("cp.async.cg.shared.global [%0], [%1], 16;" :: "r"(dst), "l"(src))
#define CP_COMMIT() asm volatile("cp.async.commit_group;" ::: "memory")
#define CP_WAIT(n)  asm volatile("cp.async.wait_group %0;" :: "n"(n) : "memory")

#define LDSM4(r0, r1, r2, r3, addr) \
    asm volatile("ldmatrix.sync.aligned.m8n8.x4.shared.b16 {%0,%1,%2,%3}, [%4];" \
        : "=r"(r0), "=r"(r1), "=r"(r2), "=r"(r3) : "r"(addr))
#define LDSM4T(r0, r1, r2, r3, addr) \
    asm volatile("ldmatrix.sync.aligned.m8n8.x4.trans.shared.b16 {%0,%1,%2,%3}, [%4];" \
        : "=r"(r0), "=r"(r1), "=r"(r2), "=r"(r3) : "r"(addr))

__device__ __forceinline__ void mma16(float* d,
    uint32_t a0, uint32_t a1, uint32_t a2, uint32_t a3,
    uint32_t b0, uint32_t b1)
{
    asm("mma.sync.aligned.m16n8k16.row.col.f32.f16.f16.f32 "
        "{%0,%1,%2,%3},{%4,%5,%6,%7},{%8,%9},{%0,%1,%2,%3};"
        : "+f"(d[0]), "+f"(d[1]), "+f"(d[2]), "+f"(d[3])
        : "r"(a0), "r"(a1), "r"(a2), "r"(a3), "r"(b0), "r"(b1));
}

// ---------------------------------------------------------------------------
// fp32 -> fp16 elementwise (8/thread)
// ---------------------------------------------------------------------------
__global__ void f2h(const float* __restrict__ x, __half* __restrict__ y, int n)
{
    int i = (blockIdx.x * blockDim.x + threadIdx.x) * 8;
    if (i >= n) return;
    float4 v0 = *(const float4*)(x + i);
    float4 v1 = *(const float4*)(x + i + 4);
    uint4 o = make_uint4(packh2(v0.x, v0.y), packh2(v0.z, v0.w),
                         packh2(v1.x, v1.y), packh2(v1.z, v1.w));
    *(uint4*)(y + i) = o;
}

// ---------------------------------------------------------------------------
// uc[row] = mean over C
// ---------------------------------------------------------------------------
__global__ void uc_kernel(const float* __restrict__ xu, float* __restrict__ uc)
{
    int warp = (blockIdx.x * blockDim.x + threadIdx.x) >> 5;
    int lane = threadIdx.x & 31;
    if (warp >= Mrows) return;
    const float* row = xu + (size_t)warp * Cdim;
    float s = 0.0f;
#pragma unroll
    for (int i = 0; i < Cdim / 32; i++) s += row[lane + i * 32];
#pragma unroll
    for (int m = 16; m; m >>= 1) s += __shfl_xor_sync(0xffffffffu, s, m);
    if (lane == 0) uc[warp] = s * (1.0f / Cdim);
}

// ---------------------------------------------------------------------------
// fp16 GEMM: Y = A[M,K] @ W^T (W [Nc,K] row-major), fp32 accum.
// 128x128 tile, BK=32, 8 warps (64x32), ldmatrix frags, cp.async 2-stage.
// HEAD_REMAP: write half into [B,H,N,D], optional rowscale (uc*SCALE).
// else: write fp32 + bias into [M,Nc].
// ---------------------------------------------------------------------------
#define GH_STRIDE 40
#define GH_STG    (2 * 128 * GH_STRIDE)     // halves per stage (A+W)
#define GH_SMEM   (2 * GH_STG * 2)          // 40960 bytes

template<int HEAD_REMAP, int HAS_BIAS>
__global__ __launch_bounds__(256, 2) void gemm_h(
    const __half* __restrict__ A, const __half* __restrict__ W,
    const float* __restrict__ bias, const float* __restrict__ rowscale,
    void* __restrict__ Yv)
{
    extern __shared__ __half hs[];
    int t = threadIdx.x, wid = t >> 5, lane = t & 31;
    int r = lane >> 2, c = lane & 3;
    int wm = (wid >> 2) * 64, wn = (wid & 3) * 32;
    int m0 = blockIdx.y * 128, n0 = blockIdx.x * 128;
    uint32_t sbase = smem_u32(hs);

    float acc[4][4][4];
#pragma unroll
    for (int mt = 0; mt < 4; mt++)
#pragma unroll
        for (int nt = 0; nt < 4; nt++)
#pragma unroll
            for (int i = 0; i < 4; i++) acc[mt][nt][i] = 0.0f;

#define GH_PREFETCH(kt) do {                                                     \
    int _s = (kt) & 1;                                                           \
    uint32_t _dA = sbase + (_s * GH_STG) * 2;                                    \
    uint32_t _dW = _dA + 128 * GH_STRIDE * 2;                                    \
    int _kb = (kt) * 32;                                                         \
    _Pragma("unroll")                                                            \
    for (int j = 0; j < 2; j++) {                                                \
        int idx = t * 2 + j;                                                     \
        int row = idx >> 2, ch = idx & 3;                                        \
        CP16(_dA + (row * GH_STRIDE + ch * 8) * 2,                               \
             A + (size_t)(m0 + row) * Cdim + _kb + ch * 8);                      \
        CP16(_dW + (row * GH_STRIDE + ch * 8) * 2,                               \
             W + (size_t)(n0 + row) * Cdim + _kb + ch * 8);                      \
    }                                                                            \
} while (0)

    GH_PREFETCH(0);
    CP_COMMIT();

    int gi = lane & 7;            // row-in-group for ldmatrix
    int gk = (lane >> 3) & 1;     // 8-row group select
    int gh = lane >> 4;           // k-halve select

    const int NT = Cdim / 32;     // 24
    for (int kt = 0; kt < NT; kt++) {
        if (kt + 1 < NT) { GH_PREFETCH(kt + 1); CP_COMMIT(); CP_WAIT(1); }
        else             { CP_WAIT(0); }
        __syncthreads();

        uint32_t sA = sbase + ((kt & 1) * GH_STG) * 2;
        uint32_t sW = sA + 128 * GH_STRIDE * 2;
#pragma unroll
        for (int kk = 0; kk < 32; kk += 16) {
            uint32_t a[4][4], bb[2][4];
#pragma unroll
            for (int mt = 0; mt < 4; mt++) {
                int row = wm + mt * 16 + gi + gk * 8;
                int col = kk + gh * 8;
                LDSM4(a[mt][0], a[mt][1], a[mt][2], a[mt][3],
                      sA + (row * GH_STRIDE + col) * 2);
            }
#pragma unroll
            for (int bt = 0; bt < 2; bt++) {
                int row = wn + bt * 16 + gi + gk * 8;
                int col = kk + gh * 8;
                LDSM4(bb[bt][0], bb[bt][1], bb[bt][2], bb[bt][3],
                      sW + (row * GH_STRIDE + col) * 2);
            }
#pragma unroll
            for (int mt = 0; mt < 4; mt++)
#pragma unroll
                for (int nt = 0; nt < 4; nt++) {
                    int bt = nt >> 1, od = nt & 1;
                    mma16(acc[mt][nt], a[mt][0], a[mt][1], a[mt][2], a[mt][3],
                          bb[bt][od ? 1 : 0], bb[bt][od ? 3 : 2]);
                }
        }
        __syncthreads();
    }

    // Epilogue
#pragma unroll
    for (int mt = 0; mt < 4; mt++) {
        int mA = m0 + wm + mt * 16 + r;
        int mB = mA + 8;
        float sA = 1.0f, sB = 1.0f;
        if (HEAD_REMAP && rowscale) {
            sA = rowscale[mA] * SCALE_F;
            sB = rowscale[mB] * SCALE_F;
        }
#pragma unroll
        for (int nt = 0; nt < 4; nt++) {
            int n = n0 + wn + nt * 8 + 2 * c;
            if (HEAD_REMAP) {
                __half* Yh = (__half*)Yv;
                int h = n >> 6, d = n & 63;
                int bA = mA >> 11, nA = mA & (Nseq - 1);
                int bB = mB >> 11, nB = mB & (Nseq - 1);
                *(uint32_t*)&Yh[(((size_t)(bA * Hn + h) * Nseq + nA) << 6) + d] =
                    packh2(acc[mt][nt][0] * sA, acc[mt][nt][1] * sA);
                *(uint32_t*)&Yh[(((size_t)(bB * Hn + h) * Nseq + nB) << 6) + d] =
                    packh2(acc[mt][nt][2] * sB, acc[mt][nt][3] * sB);
            } else {
                float* Yf = (float*)Yv;
                float2 lo = make_float2(acc[mt][nt][0], acc[mt][nt][1]);
                float2 hi = make_float2(acc[mt][nt][2], acc[mt][nt][3]);
                if (HAS_BIAS) {
                    float2 bv = *(const float2*)&bias[n];
                    lo.x += bv.x; lo.y += bv.y; hi.x += bv.x; hi.y += bv.y;
                }
                *(float2*)&Yf[(size_t)mA * Cdim + n] = lo;
                *(float2*)&Yf[(size_t)mB * Cdim + n] = hi;
            }
        }
    }
}

// ---------------------------------------------------------------------------
// fp16 flash attention: 128 q/CTA, 64-key tiles double-buffered, 8 warps,
// warp = 16 q-rows x 64 keys. P kept in registers (C-frag == A-frag).
// ---------------------------------------------------------------------------
#define AT_STRIDE 72
#define AT_QS     (128 * AT_STRIDE)                 // halves
#define AT_KV     (64 * AT_STRIDE)
#define AT_SMEM   ((AT_QS + 4 * AT_KV) * 2)         // 55296 bytes

__global__ __launch_bounds__(256, 2) void attn_h(
    const __half* __restrict__ Q, const __half* __restrict__ K,
    const __half* __restrict__ V, __half* __restrict__ O)
{
    extern __shared__ __half hs[];
    uint32_t sQ = smem_u32(hs);
    uint32_t sK0 = sQ + AT_QS * 2;          // Ks[2], Vs[2]
    uint32_t sV0 = sK0 + 2 * AT_KV * 2;

    int t = threadIdx.x, wid = t >> 5, lane = t & 31;
    int r = lane >> 2, c = lane & 3;
    int gi = lane & 7, gk = (lane >> 3) & 1, gh = lane >> 4;
    int bh = blockIdx.y;
    int b = bh / Hn, h = bh - b * Hn;
    int q0 = blockIdx.x * 128;
    int wm = wid * 16;

    const __half* Qb = Q + ((size_t)bh * Nseq + q0) * Dh;
    const __half* Kb = K + (size_t)bh * Nseq * Dh;
    const __half* Vb = V + (size_t)bh * Nseq * Dh;

    // Stage Q (cp.async): 128 rows x 8 chunks
#pragma unroll
    for (int j = 0; j < 4; j++) {
        int idx = t * 4 + j;
        int row = idx >> 3, ch = idx & 7;
        CP16(sQ + (row * AT_STRIDE + ch * 8) * 2,
             Qb + (size_t)row * Dh + ch * 8);
    }

#define AT_PREFETCH(buf, kt) do {                                                \
    uint32_t _k = sK0 + (buf) * AT_KV * 2;                                       \
    uint32_t _v = sV0 + (buf) * AT_KV * 2;                                       \
    _Pragma("unroll")                                                            \
    for (int j = 0; j < 4; j++) {                                                \
        int idx = t * 4 + j;                                                     \
        int tensor = idx >> 9, rem = idx & 511;                                  \
        int row = rem >> 3, ch = rem & 7;                                        \
        uint32_t dst = (tensor ? _v : _k) + (row * AT_STRIDE + ch * 8) * 2;      \
        const __half* src = (tensor ? Vb : Kb) + (size_t)((kt) + row) * Dh + ch * 8; \
        CP16(dst, src);                                                          \
    }                                                                            \
} while (0)

    AT_PREFETCH(0, 0);
    CP_COMMIT();

    float m_[2] = { -1e30f, -1e30f };
    float l_[2] = { 0.0f, 0.0f };
    float o[8][4];
#pragma unroll
    for (int nt = 0; nt < 8; nt++)
#pragma unroll
        for (int i = 0; i < 4; i++) o[nt][i] = 0.0f;

    const int NKT = Nseq / 64;   // 32
    for (int it = 0; it < NKT; it++) {
        int buf = it & 1;
        if (it + 1 < NKT) { AT_PREFETCH(buf ^ 1, (it + 1) * 64); CP_COMMIT(); CP_WAIT(1); }
        else              { CP_WAIT(0); }
        __syncthreads();

        uint32_t sK = sK0 + buf * AT_KV * 2;
        uint32_t sV = sV0 + buf * AT_KV * 2;

        // ---- S = Q K^T  (16 x 64 per warp) ----
        float s[8][4];
#pragma unroll
        for (int nt = 0; nt < 8; nt++)
#pragma unroll
            for (int i = 0; i < 4; i++) s[nt][i] = 0.0f;

#pragma unroll
        for (int ks = 0; ks < 4; ks++) {
            int d0 = ks * 16;
            uint32_t a0, a1, a2, a3;
            LDSM4(a0, a1, a2, a3,
                  sQ + ((wm + gi + gk * 8) * AT_STRIDE + d0 + gh * 8) * 2);
#pragma unroll
            for (int kn = 0; kn < 4; kn++) {
                uint32_t b0, b1, b2, b3;
                LDSM4(b0, b1, b2, b3,
                      sK + ((kn * 16 + gi + gk * 8) * AT_STRIDE + d0 + gh * 8) * 2);
                mma16(s[kn * 2    ], a0, a1, a2, a3, b0, b2);
                mma16(s[kn * 2 + 1], a0, a1, a2, a3, b1, b3);
            }
        }

        // ---- online softmax (2 rows/thread) ----
        float mx0 = -1e30f, mx1 = -1e30f;
#pragma unroll
        for (int nt = 0; nt < 8; nt++) {
            mx0 = fmaxf(mx0, fmaxf(s[nt][0], s[nt][1]));
            mx1 = fmaxf(mx1, fmaxf(s[nt][2], s[nt][3]));
        }
        mx0 = fmaxf(mx0, __shfl_xor_sync(0xffffffffu, mx0, 1));
        mx0 = fmaxf(mx0, __shfl_xor_sync(0xffffffffu, mx0, 2));
        mx1 = fmaxf(mx1, __shfl_xor_sync(0xffffffffu, mx1, 1));
        mx1 = fmaxf(mx1, __shfl_xor_sync(0xffffffffu, mx1, 2));

        float mn0 = fmaxf(m_[0], mx0);
        float mn1 = fmaxf(m_[1], mx1);
        float cor0 = __expf(m_[0] - mn0);
        float cor1 = __expf(m_[1] - mn1);
        m_[0] = mn0; m_[1] = mn1;

        float sum0 = 0.0f, sum1 = 0.0f;
#pragma unroll
        for (int nt = 0; nt < 8; nt++) {
            s[nt][0] = __expf(s[nt][0] - mn0);
            s[nt][1] = __expf(s[nt][1] - mn0);
            s[nt][2] = __expf(s[nt][2] - mn1);
            s[nt][3] = __expf(s[nt][3] - mn1);
            sum0 += s[nt][0] + s[nt][1];
            sum1 += s[nt][2] + s[nt][3];
        }
        sum0 += __shfl_xor_sync(0xffffffffu, sum0, 1);
        sum0 += __shfl_xor_sync(0xffffffffu, sum0, 2);
        sum1 += __shfl_xor_sync(0xffffffffu, sum1, 1);
        sum1 += __shfl_xor_sync(0xffffffffu, sum1, 2);
        l_[0] = l_[0] * cor0 + sum0;
        l_[1] = l_[1] * cor1 + sum1;

#pragma unroll
        for (int nt = 0; nt < 8; nt++) {
            o[nt][0] *= cor0; o[nt][1] *= cor0;
            o[nt][2] *= cor1; o[nt][3] *= cor1;
        }

        // ---- O += P V  (P in registers: C-frag -> A-frag) ----
#pragma unroll
        for (int ks = 0; ks < 4; ks++) {
            uint32_t pa0 = packh2(s[2 * ks][0],     s[2 * ks][1]);
            uint32_t pa1 = packh2(s[2 * ks][2],     s[2 * ks][3]);
            uint32_t pa2 = packh2(s[2 * ks + 1][0], s[2 * ks + 1][1]);
            uint32_t pa3 = packh2(s[2 * ks + 1][2], s[2 * ks + 1][3]);
#pragma unroll
            for (int dn = 0; dn < 4; dn++) {
                uint32_t b0, b1, b2, b3;
                // trans: groups (k-half via gk, n-half via gh)
                LDSM4T(b0, b1, b2, b3,
                       sV + ((ks * 16 + gi + gk * 8) * AT_STRIDE + dn * 16 + gh * 8) * 2);
                mma16(o[dn * 2    ], pa0, pa1, pa2, pa3, b0, b1);
                mma16(o[dn * 2 + 1], pa0, pa1, pa2, pa3, b2, b3);
            }
        }
        __syncthreads();   // done reading this K/V buffer before it is re-staged
    }

    // Epilogue: normalize, write half [B,N,C]
    float inv0 = 1.0f / l_[0];
    float inv1 = 1.0f / l_[1];
    int qg0 = q0 + wm + r;
    int qg1 = qg0 + 8;
#pragma unroll
    for (int nt = 0; nt < 8; nt++) {
        int d = h * Dh + nt * 8 + 2 * c;
        *(uint32_t*)&O[(size_t)(b * Nseq + qg0) * Cdim + d] =
            packh2(o[nt][0] * inv0, o[nt][1] * inv0);
        *(uint32_t*)&O[(size_t)(b * Nseq + qg1) * Cdim + d] =
            packh2(o[nt][2] * inv1, o[nt][3] * inv1);
    }
}

// ---------------------------------------------------------------------------
extern "C" void kernel_launch(void* const* d_in, const int* in_sizes, int n_in,
                              void* d_out, int out_size)
{
    const float* x_q = (const float*)d_in[0];
    const float* x_k = (const float*)d_in[1];
    const float* x_v = (const float*)d_in[2];
    const float* x_u = (const float*)d_in[3];
    const float* Wq  = (const float*)d_in[4];
    const float* Wk  = (const float*)d_in[5];
    const float* Wv  = (const float*)d_in[6];
    const float* Wp  = (const float*)d_in[7];
    const float* bp  = (const float*)d_in[8];
    float* out = (float*)d_out;

    __half *hxq, *hxk, *hxv, *hwq, *hwk, *hwv, *hwp, *hq, *hk, *hv, *ho;
    float *guc;
    cudaGetSymbolAddress((void**)&hxq, g_xq);
    cudaGetSymbolAddress((void**)&hxk, g_xk);
    cudaGetSymbolAddress((void**)&hxv, g_xv);
    cudaGetSymbolAddress((void**)&hwq, g_wq);
    cudaGetSymbolAddress((void**)&hwk, g_wk);
    cudaGetSymbolAddress((void**)&hwv, g_wv);
    cudaGetSymbolAddress((void**)&hwp, g_wp);
    cudaGetSymbolAddress((void**)&hq,  g_q);
    cudaGetSymbolAddress((void**)&hk,  g_k);
    cudaGetSymbolAddress((void**)&hv,  g_v);
    cudaGetSymbolAddress((void**)&ho,  g_o);
    cudaGetSymbolAddress((void**)&guc, g_uc);

    cudaFuncSetAttribute(attn_h, cudaFuncAttributeMaxDynamicSharedMemorySize, AT_SMEM);
    cudaFuncSetAttribute(gemm_h<1, 0>, cudaFuncAttributeMaxDynamicSharedMemorySize, GH_SMEM);
    cudaFuncSetAttribute(gemm_h<0, 1>, cudaFuncAttributeMaxDynamicSharedMemorySize, GH_SMEM);

    const int NX = Mrows * Cdim;    // 6291456
    const int NW = Cdim * Cdim;     // 589824
    f2h<<<NX / 2048, 256>>>(x_q, hxq, NX);
    f2h<<<NX / 2048, 256>>>(x_k, hxk, NX);
    f2h<<<NX / 2048, 256>>>(x_v, hxv, NX);
    f2h<<<NW / 2048, 256>>>(Wq, hwq, NW);
    f2h<<<NW / 2048, 256>>>(Wk, hwk, NW);
    f2h<<<NW / 2048, 256>>>(Wv, hwv, NW);
    f2h<<<NW / 2048, 256>>>(Wp, hwp, NW);

    uc_kernel<<<Mrows / 8, 256>>>(x_u, guc);

    dim3 gemm_grid(Cdim / 128, Mrows / 128);   // (6, 64)
    gemm_h<1, 0><<<gemm_grid, 256, GH_SMEM>>>(hxq, hwq, nullptr, guc, hq);
    gemm_h<1, 0><<<gemm_grid, 256, GH_SMEM>>>(hxk, hwk, nullptr, nullptr, hk);
    gemm_h<1, 0><<<gemm_grid, 256, GH_SMEM>>>(hxv, hwv, nullptr, nullptr, hv);

    dim3 attn_grid(Nseq / 128, Bsz * Hn);      // (16, 48)
    attn_h<<<attn_grid, 256, AT_SMEM>>>(hq, hk, hv, ho);

    gemm_h<0, 1><<<gemm_grid, 256, GH_SMEM>>>(ho, hwp, bp, nullptr, out);
}

// round 8
// speedup vs baseline: 2.4639x; 1.1500x over previous
#include <cuda_runtime.h>
#include <cuda_fp16.h>
#include <cstdint>

#define Bsz  4
#define Nseq 2048
#define Cdim 768
#define Hn   12
#define Dh   64
#define Mrows (Bsz * Nseq)   // 8192
#define SCALE_F 0.125f
#define LOG2E_F 1.4426950408889634f

// Scratch
__device__ __half g_wq[Cdim * Cdim];
__device__ __half g_wk[Cdim * Cdim];
__device__ __half g_wv[Cdim * Cdim];
__device__ __half g_wp[Cdim * Cdim];
__device__ __half g_q[Mrows * Cdim];   // [B,H,N,D], uc*SCALE*log2e folded
__device__ __half g_k[Mrows * Cdim];   // [B,H,N,D]
__device__ __half g_v[Mrows * Cdim];   // [B,H,N,D]
__device__ __half g_o[Mrows * Cdim];   // [B,N,C]
__device__ float  g_uc[Mrows];

// ---------------------------------------------------------------------------
__device__ __forceinline__ float ex2f(float x) {
    float y;
    asm("ex2.approx.f32 %0, %1;" : "=f"(y) : "f"(x));
    return y;
}
__device__ __forceinline__ uint32_t smem_u32(const void* p) {
    uint32_t a;
    asm("{ .reg .u64 t; cvta.to.shared.u64 t, %1; cvt.u32.u64 %0, t; }" : "=r"(a) : "l"(p));
    return a;
}
__device__ __forceinline__ uint32_t packh2(float a, float b) {
    __half2 h = __floats2half2_rn(a, b);
    return *(uint32_t*)&h;
}
#define CP16(dst, src) \
    asm volatile("cp.async.cg.shared.global [%0], [%1], 16;" :: "r"(dst), "l"(src))
#define CP_COMMIT() asm volatile("cp.async.commit_group;" ::: "memory")
#define CP_WAIT(n)  asm volatile("cp.async.wait_group %0;" :: "n"(n) : "memory")

#define LDSM4(r0, r1, r2, r3, addr) \
    asm volatile("ldmatrix.sync.aligned.m8n8.x4.shared.b16 {%0,%1,%2,%3}, [%4];" \
        : "=r"(r0), "=r"(r1), "=r"(r2), "=r"(r3) : "r"(addr))
#define LDSM4T(r0, r1, r2, r3, addr) \
    asm volatile("ldmatrix.sync.aligned.m8n8.x4.trans.shared.b16 {%0,%1,%2,%3}, [%4];" \
        : "=r"(r0), "=r"(r1), "=r"(r2), "=r"(r3) : "r"(addr))

__device__ __forceinline__ void mma16(float* d,
    uint32_t a0, uint32_t a1, uint32_t a2, uint32_t a3,
    uint32_t b0, uint32_t b1)
{
    asm("mma.sync.aligned.m16n8k16.row.col.f32.f16.f16.f32 "
        "{%0,%1,%2,%3},{%4,%5,%6,%7},{%8,%9},{%0,%1,%2,%3};"
        : "+f"(d[0]), "+f"(d[1]), "+f"(d[2]), "+f"(d[3])
        : "r"(a0), "r"(a1), "r"(a2), "r"(a3), "r"(b0), "r"(b1));
}

// ---------------------------------------------------------------------------
// One fused fp32->fp16 pass for the 4 weight matrices
// ---------------------------------------------------------------------------
__global__ void f2h4(const float* __restrict__ w0, const float* __restrict__ w1,
                     const float* __restrict__ w2, const float* __restrict__ w3,
                     __half* __restrict__ y0, __half* __restrict__ y1,
                     __half* __restrict__ y2, __half* __restrict__ y3)
{
    int which = blockIdx.y;
    const float* x = which == 0 ? w0 : which == 1 ? w1 : which == 2 ? w2 : w3;
    __half* y = which == 0 ? y0 : which == 1 ? y1 : which == 2 ? y2 : y3;
    int i = (blockIdx.x * blockDim.x + threadIdx.x) * 8;
    if (i >= Cdim * Cdim) return;
    float4 v0 = *(const float4*)(x + i);
    float4 v1 = *(const float4*)(x + i + 4);
    *(uint4*)(y + i) = make_uint4(packh2(v0.x, v0.y), packh2(v0.z, v0.w),
                                  packh2(v1.x, v1.y), packh2(v1.z, v1.w));
}

// ---------------------------------------------------------------------------
__global__ void uc_kernel(const float* __restrict__ xu, float* __restrict__ uc)
{
    int warp = (blockIdx.x * blockDim.x + threadIdx.x) >> 5;
    int lane = threadIdx.x & 31;
    if (warp >= Mrows) return;
    const float* row = xu + (size_t)warp * Cdim;
    float s = 0.0f;
#pragma unroll
    for (int i = 0; i < Cdim / 32; i++) s += row[lane + i * 32];
#pragma unroll
    for (int m = 16; m; m >>= 1) s += __shfl_xor_sync(0xffffffffu, s, m);
    if (lane == 0) uc[warp] = s * (1.0f / Cdim);
}

// ---------------------------------------------------------------------------
// Fused QKV projection GEMM, z-batched: Y_z = X_z[M,K] @ W_z^T, fp32 inputs
// converted to fp16 during A-staging; W pre-converted fp16 via cp.async.
// 128x128 tile, BK=32, 8 warps (64x32). Epilogue: head-remap, Q gets
// uc*SCALE*log2e rowscale.
// ---------------------------------------------------------------------------
#define GQ_STRIDE  40
#define GQ_A_BYTES (128 * GQ_STRIDE * 2)   // 10240
#define GQ_SMEM    (3 * GQ_A_BYTES)        // A + 2 W bufs = 30720

__global__ __launch_bounds__(256, 2) void gemm_qkv(
    const float* __restrict__ xq, const float* __restrict__ xk,
    const float* __restrict__ xv,
    const __half* __restrict__ wq, const __half* __restrict__ wk,
    const __half* __restrict__ wv,
    const float* __restrict__ uc,
    __half* __restrict__ yq, __half* __restrict__ yk, __half* __restrict__ yv)
{
    extern __shared__ __half hs[];
    int z = blockIdx.z;
    const float*  A = z == 0 ? xq : z == 1 ? xk : xv;
    const __half* W = z == 0 ? wq : z == 1 ? wk : wv;
    __half*       Y = z == 0 ? yq : z == 1 ? yk : yv;

    int t = threadIdx.x, wid = t >> 5, lane = t & 31;
    int r = lane >> 2, c = lane & 3;
    int gi = lane & 7, gk = (lane >> 3) & 1, gh = lane >> 4;
    int wm = (wid >> 2) * 64, wn = (wid & 3) * 32;
    int m0 = blockIdx.y * 128, n0 = blockIdx.x * 128;
    uint32_t sA  = smem_u32(hs);
    uint32_t sW0 = sA + GQ_A_BYTES;

    float acc[4][4][4];
#pragma unroll
    for (int mt = 0; mt < 4; mt++)
#pragma unroll
        for (int nt = 0; nt < 4; nt++)
#pragma unroll
            for (int i = 0; i < 4; i++) acc[mt][nt][i] = 0.0f;

    int arow = t >> 1, acg = (t & 1) * 16;
    const float* Ap = A + (size_t)(m0 + arow) * Cdim + acg;
    float4 a4[4];

#define QKV_LOADA(kt) do { int _kb = (kt) * 32;                                  \
    a4[0] = *(const float4*)(Ap + _kb);      a4[1] = *(const float4*)(Ap + _kb + 4);  \
    a4[2] = *(const float4*)(Ap + _kb + 8);  a4[3] = *(const float4*)(Ap + _kb + 12); \
} while (0)

#define QKV_STSA() do {                                                          \
    uint4 u0 = make_uint4(packh2(a4[0].x, a4[0].y), packh2(a4[0].z, a4[0].w),    \
                          packh2(a4[1].x, a4[1].y), packh2(a4[1].z, a4[1].w));   \
    uint4 u1 = make_uint4(packh2(a4[2].x, a4[2].y), packh2(a4[2].z, a4[2].w),    \
                          packh2(a4[3].x, a4[3].y), packh2(a4[3].z, a4[3].w));   \
    *(uint4*)((char*)hs + (arow * GQ_STRIDE + acg) * 2) = u0;                    \
    *(uint4*)((char*)hs + (arow * GQ_STRIDE + acg + 8) * 2) = u1;                \
} while (0)

#define QKV_CPW(kt) do { int _kb = (kt) * 32;                                    \
    uint32_t _bw = sW0 + ((kt) & 1) * GQ_A_BYTES;                                \
    _Pragma("unroll")                                                            \
    for (int j = 0; j < 2; j++) {                                                \
        int idx = t * 2 + j;                                                     \
        int row = idx >> 2, ch = idx & 3;                                        \
        CP16(_bw + (row * GQ_STRIDE + ch * 8) * 2,                               \
             W + (size_t)(n0 + row) * Cdim + _kb + ch * 8);                      \
    }                                                                            \
} while (0)

    QKV_LOADA(0);
    QKV_CPW(0); CP_COMMIT();
    QKV_STSA();
    __syncthreads();

    const int NT = Cdim / 32;   // 24
    for (int kt = 0; kt < NT; kt++) {
        if (kt + 1 < NT) { QKV_LOADA(kt + 1); QKV_CPW(kt + 1); CP_COMMIT(); }
        if (kt < NT - 1) { CP_WAIT(1); } else { CP_WAIT(0); }
        __syncthreads();   // W(kt) landed; A(kt) STS visible

        uint32_t bW = sW0 + (kt & 1) * GQ_A_BYTES;
#pragma unroll
        for (int kk = 0; kk < 32; kk += 16) {
            uint32_t a[4][4], bb[2][4];
#pragma unroll
            for (int mt = 0; mt < 4; mt++)
                LDSM4(a[mt][0], a[mt][1], a[mt][2], a[mt][3],
                      sA + ((wm + mt * 16 + gi + gk * 8) * GQ_STRIDE + kk + gh * 8) * 2);
#pragma unroll
            for (int bt = 0; bt < 2; bt++)
                LDSM4(bb[bt][0], bb[bt][1], bb[bt][2], bb[bt][3],
                      bW + ((wn + bt * 16 + gi + gk * 8) * GQ_STRIDE + kk + gh * 8) * 2);
#pragma unroll
            for (int mt = 0; mt < 4; mt++)
#pragma unroll
                for (int nt = 0; nt < 4; nt++) {
                    int bt = nt >> 1, od = nt & 1;
                    mma16(acc[mt][nt], a[mt][0], a[mt][1], a[mt][2], a[mt][3],
                          bb[bt][od ? 1 : 0], bb[bt][od ? 3 : 2]);
                }
        }
        __syncthreads();   // done reading A buf
        if (kt + 1 < NT) QKV_STSA();
    }

    // Epilogue: head-remap, Q rowscale = uc * SCALE * log2e
#pragma unroll
    for (int mt = 0; mt < 4; mt++) {
        int mA = m0 + wm + mt * 16 + r;
        int mB = mA + 8;
        float sAs = 1.0f, sBs = 1.0f;
        if (z == 0) {
            sAs = uc[mA] * (SCALE_F * LOG2E_F);
            sBs = uc[mB] * (SCALE_F * LOG2E_F);
        }
        int bA = mA >> 11, nA = mA & (Nseq - 1);
        int bB = mB >> 11, nB = mB & (Nseq - 1);
#pragma unroll
        for (int nt = 0; nt < 4; nt++) {
            int n = n0 + wn + nt * 8 + 2 * c;
            int h = n >> 6, d = n & 63;
            *(uint32_t*)&Y[(((size_t)(bA * Hn + h) * Nseq + nA) << 6) + d] =
                packh2(acc[mt][nt][0] * sAs, acc[mt][nt][1] * sAs);
            *(uint32_t*)&Y[(((size_t)(bB * Hn + h) * Nseq + nB) << 6) + d] =
                packh2(acc[mt][nt][2] * sBs, acc[mt][nt][3] * sBs);
        }
    }
}

// ---------------------------------------------------------------------------
// Output GEMM: out = O[M,C] @ Wp^T + bp  (A fp16, W fp16, fp32 out)
// ---------------------------------------------------------------------------
#define GH_STRIDE 40
#define GH_STG    (2 * 128 * GH_STRIDE)
#define GH_SMEM   (2 * GH_STG * 2)          // 40960

__global__ __launch_bounds__(256, 2) void gemm_out(
    const __half* __restrict__ A, const __half* __restrict__ W,
    const float* __restrict__ bias, float* __restrict__ Y)
{
    extern __shared__ __half hs[];
    int t = threadIdx.x, wid = t >> 5, lane = t & 31;
    int r = lane >> 2, c = lane & 3;
    int gi = lane & 7, gk = (lane >> 3) & 1, gh = lane >> 4;
    int wm = (wid >> 2) * 64, wn = (wid & 3) * 32;
    int m0 = blockIdx.y * 128, n0 = blockIdx.x * 128;
    uint32_t sbase = smem_u32(hs);

    float acc[4][4][4];
#pragma unroll
    for (int mt = 0; mt < 4; mt++)
#pragma unroll
        for (int nt = 0; nt < 4; nt++)
#pragma unroll
            for (int i = 0; i < 4; i++) acc[mt][nt][i] = 0.0f;

#define GO_PREFETCH(kt) do {                                                     \
    int _s = (kt) & 1;                                                           \
    uint32_t _dA = sbase + (_s * GH_STG) * 2;                                    \
    uint32_t _dW = _dA + 128 * GH_STRIDE * 2;                                    \
    int _kb = (kt) * 32;                                                         \
    _Pragma("unroll")                                                            \
    for (int j = 0; j < 2; j++) {                                                \
        int idx = t * 2 + j;                                                     \
        int row = idx >> 2, ch = idx & 3;                                        \
        CP16(_dA + (row * GH_STRIDE + ch * 8) * 2,                               \
             A + (size_t)(m0 + row) * Cdim + _kb + ch * 8);                      \
        CP16(_dW + (row * GH_STRIDE + ch * 8) * 2,                               \
             W + (size_t)(n0 + row) * Cdim + _kb + ch * 8);                      \
    }                                                                            \
} while (0)

    GO_PREFETCH(0);
    CP_COMMIT();

    const int NT = Cdim / 32;
    for (int kt = 0; kt < NT; kt++) {
        if (kt + 1 < NT) { GO_PREFETCH(kt + 1); CP_COMMIT(); CP_WAIT(1); }
        else             { CP_WAIT(0); }
        __syncthreads();

        uint32_t sA = sbase + ((kt & 1) * GH_STG) * 2;
        uint32_t sW = sA + 128 * GH_STRIDE * 2;
#pragma unroll
        for (int kk = 0; kk < 32; kk += 16) {
            uint32_t a[4][4], bb[2][4];
#pragma unroll
            for (int mt = 0; mt < 4; mt++)
                LDSM4(a[mt][0], a[mt][1], a[mt][2], a[mt][3],
                      sA + ((wm + mt * 16 + gi + gk * 8) * GH_STRIDE + kk + gh * 8) * 2);
#pragma unroll
            for (int bt = 0; bt < 2; bt++)
                LDSM4(bb[bt][0], bb[bt][1], bb[bt][2], bb[bt][3],
                      sW + ((wn + bt * 16 + gi + gk * 8) * GH_STRIDE + kk + gh * 8) * 2);
#pragma unroll
            for (int mt = 0; mt < 4; mt++)
#pragma unroll
                for (int nt = 0; nt < 4; nt++) {
                    int bt = nt >> 1, od = nt & 1;
                    mma16(acc[mt][nt], a[mt][0], a[mt][1], a[mt][2], a[mt][3],
                          bb[bt][od ? 1 : 0], bb[bt][od ? 3 : 2]);
                }
        }
        __syncthreads();
    }

#pragma unroll
    for (int mt = 0; mt < 4; mt++) {
        int mA = m0 + wm + mt * 16 + r;
        int mB = mA + 8;
#pragma unroll
        for (int nt = 0; nt < 4; nt++) {
            int n = n0 + wn + nt * 8 + 2 * c;
            float2 bv = *(const float2*)&bias[n];
            *(float2*)&Y[(size_t)mA * Cdim + n] =
                make_float2(acc[mt][nt][0] + bv.x, acc[mt][nt][1] + bv.y);
            *(float2*)&Y[(size_t)mB * Cdim + n] =
                make_float2(acc[mt][nt][2] + bv.x, acc[mt][nt][3] + bv.y);
        }
    }
}

// ---------------------------------------------------------------------------
// fp16 flash attention: 128 q/CTA, 64-key tiles TRIPLE-buffered (1 sync/iter),
// 8 warps (16q x 64k each), P in registers, exp2 softmax (log2e in Q).
// ---------------------------------------------------------------------------
#define AT_STRIDE 72
#define AT_QS     (128 * AT_STRIDE)
#define AT_KV     (64 * AT_STRIDE)
#define AT_SMEM   ((AT_QS + 6 * AT_KV) * 2)    // 73728

__global__ __launch_bounds__(256, 2) void attn_h(
    const __half* __restrict__ Q, const __half* __restrict__ K,
    const __half* __restrict__ V, __half* __restrict__ O)
{
    extern __shared__ __half hs[];
    uint32_t sQ  = smem_u32(hs);
    uint32_t sK0 = sQ + AT_QS * 2;           // 3 K bufs
    uint32_t sV0 = sK0 + 3 * AT_KV * 2;      // 3 V bufs

    int t = threadIdx.x, wid = t >> 5, lane = t & 31;
    int r = lane >> 2, c = lane & 3;
    int gi = lane & 7, gk = (lane >> 3) & 1, gh = lane >> 4;
    int bh = blockIdx.y;
    int b = bh / Hn, h = bh - b * Hn;
    int q0 = blockIdx.x * 128;
    int wm = wid * 16;

    const __half* Qb = Q + ((size_t)bh * Nseq + q0) * Dh;
    const __half* Kb = K + (size_t)bh * Nseq * Dh;
    const __half* Vb = V + (size_t)bh * Nseq * Dh;

    // Stage Q (joins first commit group)
#pragma unroll
    for (int j = 0; j < 4; j++) {
        int idx = t * 4 + j;
        int row = idx >> 3, ch = idx & 7;
        CP16(sQ + (row * AT_STRIDE + ch * 8) * 2, Qb + (size_t)row * Dh + ch * 8);
    }

#define AT_PREFETCH(buf, kt) do {                                                \
    uint32_t _k = sK0 + (buf) * AT_KV * 2;                                       \
    uint32_t _v = sV0 + (buf) * AT_KV * 2;                                       \
    _Pragma("unroll")                                                            \
    for (int j = 0; j < 4; j++) {                                                \
        int idx = t * 4 + j;                                                     \
        int tensor = idx >> 9, rem = idx & 511;                                  \
        int row = rem >> 3, ch = rem & 7;                                        \
        uint32_t dst = (tensor ? _v : _k) + (row * AT_STRIDE + ch * 8) * 2;      \
        const __half* src = (tensor ? Vb : Kb) + (size_t)((kt) + row) * Dh + ch * 8; \
        CP16(dst, src);                                                          \
    }                                                                            \
} while (0)

    AT_PREFETCH(0, 0);  CP_COMMIT();
    AT_PREFETCH(1, 64); CP_COMMIT();

    float m_[2] = { -1e30f, -1e30f };
    float l_[2] = { 0.0f, 0.0f };
    float o[8][4];
#pragma unroll
    for (int nt = 0; nt < 8; nt++)
#pragma unroll
        for (int i = 0; i < 4; i++) o[nt][i] = 0.0f;

    const int NKT = Nseq / 64;   // 32
    int bi = 0, pf = 2;
    for (int it = 0; it < NKT; it++) {
        if (it < NKT - 1) { CP_WAIT(1); } else { CP_WAIT(0); }
        __syncthreads();   // buf(it) ready; all warps done with buf being re-targeted

        if (it + 2 < NKT) {
            AT_PREFETCH(pf, (it + 2) * 64);
            CP_COMMIT();
            pf = (pf == 2) ? 0 : pf + 1;
        }

        uint32_t sK = sK0 + bi * AT_KV * 2;
        uint32_t sV = sV0 + bi * AT_KV * 2;
        bi = (bi == 2) ? 0 : bi + 1;

        // ---- S = Q K^T ----
        float s[8][4];
#pragma unroll
        for (int nt = 0; nt < 8; nt++)
#pragma unroll
            for (int i = 0; i < 4; i++) s[nt][i] = 0.0f;

#pragma unroll
        for (int ks = 0; ks < 4; ks++) {
            int d0 = ks * 16;
            uint32_t a0, a1, a2, a3;
            LDSM4(a0, a1, a2, a3,
                  sQ + ((wm + gi + gk * 8) * AT_STRIDE + d0 + gh * 8) * 2);
#pragma unroll
            for (int kn = 0; kn < 4; kn++) {
                uint32_t b0, b1, b2, b3;
                LDSM4(b0, b1, b2, b3,
                      sK + ((kn * 16 + gi + gk * 8) * AT_STRIDE + d0 + gh * 8) * 2);
                mma16(s[kn * 2    ], a0, a1, a2, a3, b0, b2);
                mma16(s[kn * 2 + 1], a0, a1, a2, a3, b1, b3);
            }
        }

        // ---- online softmax in log2 domain ----
        float mx0 = -1e30f, mx1 = -1e30f;
#pragma unroll
        for (int nt = 0; nt < 8; nt++) {
            mx0 = fmaxf(mx0, fmaxf(s[nt][0], s[nt][1]));
            mx1 = fmaxf(mx1, fmaxf(s[nt][2], s[nt][3]));
        }
        mx0 = fmaxf(mx0, __shfl_xor_sync(0xffffffffu, mx0, 1));
        mx0 = fmaxf(mx0, __shfl_xor_sync(0xffffffffu, mx0, 2));
        mx1 = fmaxf(mx1, __shfl_xor_sync(0xffffffffu, mx1, 1));
        mx1 = fmaxf(mx1, __shfl_xor_sync(0xffffffffu, mx1, 2));

        float mn0 = fmaxf(m_[0], mx0);
        float mn1 = fmaxf(m_[1], mx1);
        float cor0 = ex2f(m_[0] - mn0);
        float cor1 = ex2f(m_[1] - mn1);
        m_[0] = mn0; m_[1] = mn1;

        float sum0 = 0.0f, sum1 = 0.0f;
#pragma unroll
        for (int nt = 0; nt < 8; nt++) {
            s[nt][0] = ex2f(s[nt][0] - mn0);
            s[nt][1] = ex2f(s[nt][1] - mn0);
            s[nt][2] = ex2f(s[nt][2] - mn1);
            s[nt][3] = ex2f(s[nt][3] - mn1);
            sum0 += s[nt][0] + s[nt][1];
            sum1 += s[nt][2] + s[nt][3];
        }
        sum0 += __shfl_xor_sync(0xffffffffu, sum0, 1);
        sum0 += __shfl_xor_sync(0xffffffffu, sum0, 2);
        sum1 += __shfl_xor_sync(0xffffffffu, sum1, 1);
        sum1 += __shfl_xor_sync(0xffffffffu, sum1, 2);
        l_[0] = l_[0] * cor0 + sum0;
        l_[1] = l_[1] * cor1 + sum1;

#pragma unroll
        for (int nt = 0; nt < 8; nt++) {
            o[nt][0] *= cor0; o[nt][1] *= cor0;
            o[nt][2] *= cor1; o[nt][3] *= cor1;
        }

        // ---- O += P V (P in registers) ----
#pragma unroll
        for (int ks = 0; ks < 4; ks++) {
            uint32_t pa0 = packh2(s[2 * ks][0],     s[2 * ks][1]);
            uint32_t pa1 = packh2(s[2 * ks][2],     s[2 * ks][3]);
            uint32_t pa2 = packh2(s[2 * ks + 1][0], s[2 * ks + 1][1]);
            uint32_t pa3 = packh2(s[2 * ks + 1][2], s[2 * ks + 1][3]);
#pragma unroll
            for (int dn = 0; dn < 4; dn++) {
                uint32_t b0, b1, b2, b3;
                LDSM4T(b0, b1, b2, b3,
                       sV + ((ks * 16 + gi + gk * 8) * AT_STRIDE + dn * 16 + gh * 8) * 2);
                mma16(o[dn * 2    ], pa0, pa1, pa2, pa3, b0, b1);
                mma16(o[dn * 2 + 1], pa0, pa1, pa2, pa3, b2, b3);
            }
        }
        // no trailing sync: 3 buffers + top-of-loop sync cover the hazard
    }

    float inv0 = 1.0f / l_[0];
    float inv1 = 1.0f / l_[1];
    int qg0 = q0 + wm + r;
    int qg1 = qg0 + 8;
#pragma unroll
    for (int nt = 0; nt < 8; nt++) {
        int d = h * Dh + nt * 8 + 2 * c;
        *(uint32_t*)&O[(size_t)(b * Nseq + qg0) * Cdim + d] =
            packh2(o[nt][0] * inv0, o[nt][1] * inv0);
        *(uint32_t*)&O[(size_t)(b * Nseq + qg1) * Cdim + d] =
            packh2(o[nt][2] * inv1, o[nt][3] * inv1);
    }
}

// ---------------------------------------------------------------------------
extern "C" void kernel_launch(void* const* d_in, const int* in_sizes, int n_in,
                              void* d_out, int out_size)
{
    const float* x_q = (const float*)d_in[0];
    const float* x_k = (const float*)d_in[1];
    const float* x_v = (const float*)d_in[2];
    const float* x_u = (const float*)d_in[3];
    const float* Wq  = (const float*)d_in[4];
    const float* Wk  = (const float*)d_in[5];
    const float* Wv  = (const float*)d_in[6];
    const float* Wp  = (const float*)d_in[7];
    const float* bp  = (const float*)d_in[8];
    float* out = (float*)d_out;

    __half *hwq, *hwk, *hwv, *hwp, *hq, *hk, *hv, *ho;
    float *guc;
    cudaGetSymbolAddress((void**)&hwq, g_wq);
    cudaGetSymbolAddress((void**)&hwk, g_wk);
    cudaGetSymbolAddress((void**)&hwv, g_wv);
    cudaGetSymbolAddress((void**)&hwp, g_wp);
    cudaGetSymbolAddress((void**)&hq,  g_q);
    cudaGetSymbolAddress((void**)&hk,  g_k);
    cudaGetSymbolAddress((void**)&hv,  g_v);
    cudaGetSymbolAddress((void**)&ho,  g_o);
    cudaGetSymbolAddress((void**)&guc, g_uc);

    cudaFuncSetAttribute(attn_h,   cudaFuncAttributeMaxDynamicSharedMemorySize, AT_SMEM);
    cudaFuncSetAttribute(gemm_qkv, cudaFuncAttributeMaxDynamicSharedMemorySize, GQ_SMEM);
    cudaFuncSetAttribute(gemm_out, cudaFuncAttributeMaxDynamicSharedMemorySize, GH_SMEM);

    const int NW = Cdim * Cdim;   // 589824
    dim3 f2h_grid(NW / 2048, 4);
    f2h4<<<f2h_grid, 256>>>(Wq, Wk, Wv, Wp, hwq, hwk, hwv, hwp);

    uc_kernel<<<Mrows / 8, 256>>>(x_u, guc);

    dim3 qkv_grid(Cdim / 128, Mrows / 128, 3);   // (6, 64, 3)
    gemm_qkv<<<qkv_grid, 256, GQ_SMEM>>>(x_q, x_k, x_v, hwq, hwk, hwv,
                                         guc, hq, hk, hv);

    dim3 attn_grid(Nseq / 128, Bsz * Hn);        // (16, 48)
    attn_h<<<attn_grid, 256, AT_SMEM>>>(hq, hk, hv, ho);

    dim3 out_grid(Cdim / 128, Mrows / 128);      // (6, 64)
    gemm_out<<<out_grid, 256, GH_SMEM>>>(ho, hwp, bp, out);
}